// round 5
// baseline (speedup 1.0000x reference)
#include <cuda_runtime.h>
#include <cuda_bf16.h>
#include <math.h>

#define BB 16

// ---------------- scratch ----------------
__device__ float  g_h0[BB*4096*32];
__device__ float  g_h1[BB*1024*64];
__device__ float  g_h2[BB*256*128];
__device__ float  g_h3[BB*64*256];
__device__ float  g_h4[BB*16*512];
__device__ float  g_p1[BB*1024*3];
__device__ float  g_p2[BB*256*3];
__device__ float  g_p3[BB*64*3];
__device__ float  g_p4[BB*16*3];
__device__ int    g_idx[BB*1024];
__device__ int    g_nidx[BB*1024*16];
__device__ float  g_feat[BB*1024*16*35];
__device__ float  g_y[BB*1024*16*64];
__device__ double g_sum[512], g_sqs[512];
__device__ float  g_scale[512], g_shift[512];
__device__ float  g_z[BB*512];
__device__ float  g_t1[BB*256];
__device__ float  g_t2[BB*128];

// ---------------- stage 0 linear ----------------
__global__ void lin0_kernel(const float* __restrict__ x, const float* __restrict__ W1,
                            float* __restrict__ h)
{
    int gid = blockIdx.x * blockDim.x + threadIdx.x;
    if (gid >= BB*4096*32) return;
    int d = gid & 31, r = gid >> 5;
    float v =        __ldg(x + r*3 + 0) * __ldg(W1 + d);
    v = fmaf(__ldg(x + r*3 + 1), __ldg(W1 + 32 + d), v);
    v = fmaf(__ldg(x + r*3 + 2), __ldg(W1 + 64 + d), v);
    h[gid] = v;
}

// ---------------- BN statistics ----------------
__global__ void zero_stats_kernel()
{
    int i = threadIdx.x;
    if (i < 512) { g_sum[i] = 0.0; g_sqs[i] = 0.0; }
}

__global__ void stats_kernel(const float* __restrict__ y, int nrows, int C)
{
    int c  = threadIdx.x;
    int r0 = blockIdx.x * blockDim.y + threadIdx.y;
    int stride = gridDim.x * blockDim.y;
    double s = 0.0, q = 0.0;
    for (int r = r0; r < nrows; r += stride) {
        float v = y[(long long)r * C + c];
        s += (double)v;
        q += (double)v * (double)v;
    }
    atomicAdd(&g_sum[c], s);
    atomicAdd(&g_sqs[c], q);
}

__global__ void finalize_bn_kernel(const float* __restrict__ g, const float* __restrict__ b,
                                   int C, double inv_n)
{
    int c = threadIdx.x;
    if (c < C) {
        double m = g_sum[c] * inv_n;
        double v = g_sqs[c] * inv_n - m * m;
        float rstd = (float)rsqrt(v + 1e-5);
        float sc = __ldg(g + c) * rstd;
        g_scale[c] = sc;
        g_shift[c] = __ldg(b + c) - (float)m * sc;
    }
}

__global__ void bnrelu32_kernel(float* __restrict__ h, int total)
{
    int gid = blockIdx.x * blockDim.x + threadIdx.x;
    if (gid >= total) return;
    int c = gid & 31;
    float v = fmaf(h[gid], g_scale[c], g_shift[c]);
    h[gid] = v > 0.f ? v : 0.f;
}

// ---------------- FPS ----------------
template<int N, int M, int T>
__global__ void __launch_bounds__(T) fps_kernel(const float* __restrict__ p, int* __restrict__ out_idx)
{
    constexpr int P = N / T;
    int b = blockIdx.x;
    const float* pb = p + (long long)b * N * 3;
    int tid = threadIdx.x;

    float px[P], py[P], pz[P], md[P];
#pragma unroll
    for (int i = 0; i < P; i++) {
        int n = tid + i * T;
        px[i] = pb[3*n]; py[i] = pb[3*n+1]; pz[i] = pb[3*n+2];
        md[i] = 3.4e38f;
    }

    __shared__ unsigned s_val[T/32 > 0 ? T/32 : 1];
    __shared__ unsigned s_idx[T/32 > 0 ? T/32 : 1];
    __shared__ int s_last;
    int last = 0;

    for (int m = 0; m < M; m++) {
        if (tid == 0) out_idx[b*M + m] = last;
        float lx = __ldg(pb + 3*last);
        float ly = __ldg(pb + 3*last + 1);
        float lz = __ldg(pb + 3*last + 2);

        float bestv = -1.0f; unsigned besti = 0;
#pragma unroll
        for (int i = 0; i < P; i++) {
            float dx = px[i] - lx, dy = py[i] - ly, dz = pz[i] - lz;
            float d = fmaf(dx, dx, fmaf(dy, dy, dz*dz));
            float mi = fminf(md[i], d);
            md[i] = mi;
            if (mi > bestv) { bestv = mi; besti = (unsigned)(tid + i*T); }
        }
        unsigned fb = __float_as_uint(bestv);
        unsigned wmax = __reduce_max_sync(0xffffffffu, fb);
        unsigned cand = (fb == wmax) ? besti : 0xffffffffu;
        unsigned widx = __reduce_min_sync(0xffffffffu, cand);
        if ((tid & 31) == 0) { s_val[tid >> 5] = wmax; s_idx[tid >> 5] = widx; }
        __syncthreads();
        if (tid < 32) {
            constexpr int NW = T / 32;
            unsigned v  = (tid < NW) ? s_val[tid] : 0u;
            unsigned ix = (tid < NW) ? s_idx[tid] : 0xffffffffu;
            unsigned m2 = __reduce_max_sync(0xffffffffu, v);
            unsigned c2 = (v == m2) ? ix : 0xffffffffu;
            unsigned i2 = __reduce_min_sync(0xffffffffu, c2);
            if (tid == 0) s_last = (int)i2;
        }
        __syncthreads();
        last = s_last;
    }
}

// ---------------- gather points ----------------
__global__ void gather_p_kernel(const float* __restrict__ p_in, const int* __restrict__ idx,
                                float* __restrict__ p_out, int N, int M)
{
    int gid = blockIdx.x * blockDim.x + threadIdx.x;
    if (gid >= BB * M * 3) return;
    int c = gid % 3;
    int m = (gid / 3) % M;
    int b = gid / (3 * M);
    p_out[gid] = p_in[((long long)b * N + idx[b*M + m]) * 3 + c];
}

// ---------------- kNN ----------------
#define KNN_TRY(PX,PY,PZ,NI) {                                                 \
    float dx = (PX) - qx, dy = (PY) - qy, dz = (PZ) - qz;                      \
    float d = fmaf(dx, dx, fmaf(dy, dy, dz*dz));                               \
    if (d < kd[15]) {                                                          \
        kd[15] = d; ki[15] = (NI);                                             \
        _Pragma("unroll")                                                      \
        for (int j = 15; j > 0; --j) {                                         \
            if (kd[j] < kd[j-1]) {                                             \
                float td = kd[j]; kd[j] = kd[j-1]; kd[j-1] = td;               \
                int   ti = ki[j]; ki[j] = ki[j-1]; ki[j-1] = ti;               \
            }                                                                  \
        }                                                                      \
    } }

template<int N, int QB>
__global__ void __launch_bounds__(QB) knn_kernel(const float* __restrict__ p,
                                                 const float* __restrict__ q,
                                                 int M, int* __restrict__ nidx)
{
    extern __shared__ float sm[];
    float* sx = sm; float* sy = sm + N; float* sz = sm + 2*N;
    int bpb = M / QB;
    int b  = blockIdx.x / bpb;
    int q0 = (blockIdx.x % bpb) * QB;
    const float* pb = p + (long long)b * N * 3;
    for (int i = threadIdx.x; i < N; i += QB) {
        sx[i] = pb[3*i]; sy[i] = pb[3*i+1]; sz[i] = pb[3*i+2];
    }
    __syncthreads();

    int qi = q0 + threadIdx.x;
    const float* qp = q + ((long long)b * M + qi) * 3;
    float qx = qp[0], qy = qp[1], qz = qp[2];

    float kd[16]; int ki[16];
#pragma unroll
    for (int i = 0; i < 16; i++) { kd[i] = 3.4e38f; ki[i] = 0; }

    for (int n0 = 0; n0 < N; n0 += 4) {
        float4 X = *reinterpret_cast<const float4*>(sx + n0);
        float4 Y = *reinterpret_cast<const float4*>(sy + n0);
        float4 Z = *reinterpret_cast<const float4*>(sz + n0);
        KNN_TRY(X.x, Y.x, Z.x, n0 + 0);
        KNN_TRY(X.y, Y.y, Z.y, n0 + 1);
        KNN_TRY(X.z, Y.z, Z.z, n0 + 2);
        KNN_TRY(X.w, Y.w, Z.w, n0 + 3);
    }
    int base = ((long long)b * M + qi) * 16;
#pragma unroll
    for (int j = 0; j < 16; j++) nidx[base + j] = ki[j];
}

// ---------------- grouped feature build ----------------
__global__ void feat_kernel(const float* __restrict__ p_in, const float* __restrict__ h_in,
                            const float* __restrict__ newp, const int* __restrict__ nidx,
                            float* __restrict__ feat, int N, int M, int Cin)
{
    int r = blockIdx.x;
    int c = threadIdx.x;
    int CK = Cin + 3;
    if (c >= CK) return;
    int m = (r >> 4) % M;
    int b = r / (16 * M);
    int n = nidx[r];
    float v;
    if (c < 3) v = p_in[((long long)b*N + n)*3 + c] - newp[((long long)b*M + m)*3 + c];
    else       v = h_in[((long long)b*N + n)*Cin + (c - 3)];
    feat[(long long)r * CK + c] = v;
}

// ---------------- fp32 tiled GEMM ----------------
__global__ void __launch_bounds__(256) gemm_kernel(const float* __restrict__ A,
                                                   const float* __restrict__ W,
                                                   float* __restrict__ C,
                                                   int rows, int CK, int COUT)
{
    __shared__ float As[16][68];
    __shared__ float Bs[16][68];
    int t = threadIdx.x;
    int row0 = blockIdx.x * 64;
    int col0 = blockIdx.y * 64;
    int tx = t & 15, ty = t >> 4;
    float acc[4][4];
#pragma unroll
    for (int i = 0; i < 4; i++)
#pragma unroll
        for (int j = 0; j < 4; j++) acc[i][j] = 0.f;

    for (int k0 = 0; k0 < CK; k0 += 16) {
#pragma unroll
        for (int j = 0; j < 4; j++) {
            int lin = t + j * 256;
            int i = lin >> 4, kk = lin & 15;
            As[kk][i] = (k0 + kk < CK) ? A[(long long)(row0 + i) * CK + k0 + kk] : 0.f;
        }
#pragma unroll
        for (int j = 0; j < 4; j++) {
            int lin = t + j * 256;
            int kk = lin >> 6, cc = lin & 63;
            Bs[kk][cc] = (k0 + kk < CK) ? W[(long long)(k0 + kk) * COUT + col0 + cc] : 0.f;
        }
        __syncthreads();
#pragma unroll
        for (int kk = 0; kk < 16; kk++) {
            float a0 = As[kk][ty*4+0], a1 = As[kk][ty*4+1], a2 = As[kk][ty*4+2], a3 = As[kk][ty*4+3];
            float b0 = Bs[kk][tx*4+0], b1 = Bs[kk][tx*4+1], b2 = Bs[kk][tx*4+2], b3 = Bs[kk][tx*4+3];
            acc[0][0]=fmaf(a0,b0,acc[0][0]); acc[0][1]=fmaf(a0,b1,acc[0][1]);
            acc[0][2]=fmaf(a0,b2,acc[0][2]); acc[0][3]=fmaf(a0,b3,acc[0][3]);
            acc[1][0]=fmaf(a1,b0,acc[1][0]); acc[1][1]=fmaf(a1,b1,acc[1][1]);
            acc[1][2]=fmaf(a1,b2,acc[1][2]); acc[1][3]=fmaf(a1,b3,acc[1][3]);
            acc[2][0]=fmaf(a2,b0,acc[2][0]); acc[2][1]=fmaf(a2,b1,acc[2][1]);
            acc[2][2]=fmaf(a2,b2,acc[2][2]); acc[2][3]=fmaf(a2,b3,acc[2][3]);
            acc[3][0]=fmaf(a3,b0,acc[3][0]); acc[3][1]=fmaf(a3,b1,acc[3][1]);
            acc[3][2]=fmaf(a3,b2,acc[3][2]); acc[3][3]=fmaf(a3,b3,acc[3][3]);
        }
        __syncthreads();
    }
#pragma unroll
    for (int i = 0; i < 4; i++)
#pragma unroll
        for (int j = 0; j < 4; j++)
            C[(long long)(row0 + ty*4 + i) * COUT + col0 + tx*4 + j] = acc[i][j];
}

// ---------------- BN + ReLU + max over k ----------------
__global__ void bnmax_kernel(const float* __restrict__ y, float* __restrict__ hout,
                             int BM, int C)
{
    int gid = blockIdx.x * blockDim.x + threadIdx.x;
    if (gid >= BM * C) return;
    int c = gid & (C - 1);
    int r = gid / C;
    const float* yp = y + (long long)r * 16 * C + c;
    float sc = g_scale[c], sh = g_shift[c];
    float mx = 0.f;
#pragma unroll
    for (int k = 0; k < 16; k++) {
        float v = fmaf(yp[(long long)k * C], sc, sh);
        mx = fmaxf(mx, v);
    }
    hout[gid] = mx;
}

// ---------------- mean pool ----------------
__global__ void mean_kernel(const float* __restrict__ h4)
{
    int gid = blockIdx.x * blockDim.x + threadIdx.x;
    if (gid >= BB * 512) return;
    int c = gid & 511, b = gid >> 9;
    float s = 0.f;
#pragma unroll
    for (int k = 0; k < 16; k++) s += h4[((long long)b * 16 + k) * 512 + c];
    g_z[gid] = s * (1.f / 16.f);
}

// ---------------- classifier head: one thread per output column ----------------
__global__ void head_kernel(const float* __restrict__ in, const float* __restrict__ W,
                            const float* __restrict__ bias,
                            const float* __restrict__ gg, const float* __restrict__ bb,
                            float* __restrict__ outp, int Cin, int Cout, int bn_relu)
{
    int j = blockIdx.x * blockDim.x + threadIdx.x;
    if (j >= Cout) return;
    float acc[16];
    float bs = __ldg(bias + j);
#pragma unroll
    for (int b = 0; b < 16; b++) acc[b] = bs;
    for (int c = 0; c < Cin; c++) {
        float w = __ldg(W + (long long)c * Cout + j);
#pragma unroll
        for (int b = 0; b < 16; b++) acc[b] = fmaf(in[b*Cin + c], w, acc[b]);
    }
    if (bn_relu) {
        float s = 0.f;
#pragma unroll
        for (int b = 0; b < 16; b++) s += acc[b];
        float m = s * (1.f/16.f);
        float v = 0.f;
#pragma unroll
        for (int b = 0; b < 16; b++) { float d = acc[b] - m; v = fmaf(d, d, v); }
        v *= (1.f/16.f);
        float sc = __ldg(gg + j) * rsqrtf(v + 1e-5f);
        float sh = __ldg(bb + j) - m * sc;
#pragma unroll
        for (int b = 0; b < 16; b++) {
            float o = fmaf(acc[b], sc, sh);
            outp[b*Cout + j] = o > 0.f ? o : 0.f;
        }
    } else {
#pragma unroll
        for (int b = 0; b < 16; b++) outp[b*Cout + j] = acc[b];
    }
}

// ---------------- host launchers ----------------
static void run_fps(const float* p, int* idx, int N, int M)
{
    if      (N == 4096) fps_kernel<4096,1024,1024><<<BB,1024>>>(p, idx);
    else if (N == 1024) fps_kernel<1024, 256,1024><<<BB,1024>>>(p, idx);
    else if (N ==  256) fps_kernel< 256,  64, 256><<<BB, 256>>>(p, idx);
    else                fps_kernel<  64,  16,  64><<<BB,  64>>>(p, idx);
}

static void run_knn(const float* p, const float* q, int N, int M, int* nidx)
{
    if      (N == 4096) knn_kernel<4096,256><<<BB*(M/256),256,3*4096*4>>>(p, q, M, nidx);
    else if (N == 1024) knn_kernel<1024,256><<<BB*(M/256),256,3*1024*4>>>(p, q, M, nidx);
    else if (N ==  256) knn_kernel< 256, 64><<<BB*(M/ 64), 64,3* 256*4>>>(p, q, M, nidx);
    else                knn_kernel<  64, 16><<<BB*(M/ 16), 16,3*  64*4>>>(p, q, M, nidx);
}

static void run_stage(const float* p_in, const float* h_in, float* p_out, float* h_out,
                      int N, int M, int Cin, int Cout,
                      const float* W, const float* g, const float* b,
                      int* idx, int* nidx, float* feat, float* y)
{
    run_fps(p_in, idx, N, M);
    int t3 = BB * M * 3;
    gather_p_kernel<<<(t3+255)/256,256>>>(p_in, idx, p_out, N, M);
    run_knn(p_in, p_out, N, M, nidx);
    int rows = BB * M * 16, CK = Cin + 3;
    int ft = ((CK + 31) / 32) * 32;
    feat_kernel<<<rows, ft>>>(p_in, h_in, p_out, nidx, feat, N, M, Cin);
    dim3 gg(rows/64, Cout/64);
    gemm_kernel<<<gg, 256>>>(feat, W, y, rows, CK, Cout);
    zero_stats_kernel<<<1,512>>>();
    dim3 sb(Cout, 1024/Cout);
    stats_kernel<<<128, sb>>>(y, rows, Cout);
    finalize_bn_kernel<<<1,512>>>(g, b, Cout, 1.0/(double)rows);
    int bm = BB * M;
    bnmax_kernel<<<(bm*Cout+255)/256,256>>>(y, h_out, bm, Cout);
}

extern "C" void kernel_launch(void* const* d_in, const int* in_sizes, int n_in,
                              void* d_out, int out_size)
{
    const float* x   = (const float*)d_in[0];
    const float* W1  = (const float*)d_in[1];
    const float* g1  = (const float*)d_in[2];
    const float* b1  = (const float*)d_in[3];
    const float* W2  = (const float*)d_in[4];
    const float* g2  = (const float*)d_in[5];
    const float* b2  = (const float*)d_in[6];
    const float* W3  = (const float*)d_in[7];
    const float* g3  = (const float*)d_in[8];
    const float* b3  = (const float*)d_in[9];
    const float* W4  = (const float*)d_in[10];
    const float* g4  = (const float*)d_in[11];
    const float* b4  = (const float*)d_in[12];
    const float* W5  = (const float*)d_in[13];
    const float* g5  = (const float*)d_in[14];
    const float* b5  = (const float*)d_in[15];
    const float* Wc1 = (const float*)d_in[16];
    const float* bc1 = (const float*)d_in[17];
    const float* gc1 = (const float*)d_in[18];
    const float* hc1 = (const float*)d_in[19];
    const float* Wc2 = (const float*)d_in[20];
    const float* bc2 = (const float*)d_in[21];
    const float* gc2 = (const float*)d_in[22];
    const float* hc2 = (const float*)d_in[23];
    const float* Wc3 = (const float*)d_in[24];
    const float* bc3 = (const float*)d_in[25];
    float* out = (float*)d_out;

    float *h0, *h1, *h2, *h3, *h4, *p1, *p2, *p3, *p4, *feat, *y, *z, *t1, *t2;
    int *idx, *nidx;
    cudaGetSymbolAddress((void**)&h0,   g_h0);
    cudaGetSymbolAddress((void**)&h1,   g_h1);
    cudaGetSymbolAddress((void**)&h2,   g_h2);
    cudaGetSymbolAddress((void**)&h3,   g_h3);
    cudaGetSymbolAddress((void**)&h4,   g_h4);
    cudaGetSymbolAddress((void**)&p1,   g_p1);
    cudaGetSymbolAddress((void**)&p2,   g_p2);
    cudaGetSymbolAddress((void**)&p3,   g_p3);
    cudaGetSymbolAddress((void**)&p4,   g_p4);
    cudaGetSymbolAddress((void**)&feat, g_feat);
    cudaGetSymbolAddress((void**)&y,    g_y);
    cudaGetSymbolAddress((void**)&z,    g_z);
    cudaGetSymbolAddress((void**)&t1,   g_t1);
    cudaGetSymbolAddress((void**)&t2,   g_t2);
    cudaGetSymbolAddress((void**)&idx,  g_idx);
    cudaGetSymbolAddress((void**)&nidx, g_nidx);

    // stage 0: h0 = relu(BN(x @ W1))
    int tot0 = BB*4096*32;
    lin0_kernel<<<(tot0+255)/256,256>>>(x, W1, h0);
    zero_stats_kernel<<<1,512>>>();
    { dim3 sb(32, 32); stats_kernel<<<128, sb>>>(h0, BB*4096, 32); }
    finalize_bn_kernel<<<1,512>>>(g1, b1, 32, 1.0/(double)(BB*4096));
    bnrelu32_kernel<<<(tot0+255)/256,256>>>(h0, tot0);

    // transition-down stages
    run_stage(x,  h0, p1, h1, 4096, 1024,  32,  64, W2, g2, b2, idx, nidx, feat, y);
    run_stage(p1, h1, p2, h2, 1024,  256,  64, 128, W3, g3, b3, idx, nidx, feat, y);
    run_stage(p2, h2, p3, h3,  256,   64, 128, 256, W4, g4, b4, idx, nidx, feat, y);
    run_stage(p3, h3, p4, h4,   64,   16, 256, 512, W5, g5, b5, idx, nidx, feat, y);

    // mean pool + head
    mean_kernel<<<(BB*512+255)/256,256>>>(h4);
    head_kernel<<<1,256>>>(z,  Wc1, bc1, gc1, hc1, t1, 512, 256, 1);
    head_kernel<<<1,128>>>(t1, Wc2, bc2, gc2, hc2, t2, 256, 128, 1);
    head_kernel<<<1, 64>>>(t2, Wc3, bc3, (const float*)0, (const float*)0, out, 128, 40, 0);
}

// round 7
// speedup vs baseline: 1.4644x; 1.4644x over previous
#include <cuda_runtime.h>
#include <cuda_bf16.h>
#include <math.h>

#define BB 16

// ---------------- scratch ----------------
__device__ float  g_h0[BB*4096*32];
__device__ float  g_h1[BB*1024*64];
__device__ float  g_h2[BB*256*128];
__device__ float  g_h3[BB*64*256];
__device__ float  g_h4[BB*16*512];
__device__ float  g_p1[BB*1024*3];
__device__ float  g_p2[BB*256*3];
__device__ float  g_p3[BB*64*3];
__device__ float  g_p4[BB*16*3];
__device__ int    g_idx[BB*1024];
__device__ int    g_nidx[BB*1024*16];
__device__ float  g_gmax[BB*1024*64];     // raw pre-BN max over k, max bm*C = 1M
__device__ double g_sum[512], g_sqs[512];
__device__ float  g_scale[512], g_shift[512];
__device__ float  g_z[BB*512];
__device__ float  g_t1[BB*256];
__device__ float  g_t2[BB*128];

// ---------------- stage 0 linear ----------------
__global__ void lin0_kernel(const float* __restrict__ x, const float* __restrict__ W1,
                            float* __restrict__ h)
{
    int gid = blockIdx.x * blockDim.x + threadIdx.x;
    if (gid >= BB*4096*32) return;
    int d = gid & 31, r = gid >> 5;
    float v =        __ldg(x + r*3 + 0) * __ldg(W1 + d);
    v = fmaf(__ldg(x + r*3 + 1), __ldg(W1 + 32 + d), v);
    v = fmaf(__ldg(x + r*3 + 2), __ldg(W1 + 64 + d), v);
    h[gid] = v;
}

// ---------------- BN statistics ----------------
__global__ void zero_stats_kernel()
{
    int i = threadIdx.x;
    if (i < 512) { g_sum[i] = 0.0; g_sqs[i] = 0.0; }
}

__global__ void stats_kernel(const float* __restrict__ y, int nrows, int C)
{
    int c  = threadIdx.x;
    int r0 = blockIdx.x * blockDim.y + threadIdx.y;
    int stride = gridDim.x * blockDim.y;
    double s = 0.0, q = 0.0;
    for (int r = r0; r < nrows; r += stride) {
        float v = y[(long long)r * C + c];
        s += (double)v;
        q += (double)v * (double)v;
    }
    atomicAdd(&g_sum[c], s);
    atomicAdd(&g_sqs[c], q);
}

__global__ void finalize_bn_kernel(const float* __restrict__ g, const float* __restrict__ b,
                                   int C, double inv_n)
{
    int c = threadIdx.x;
    if (c < C) {
        double m = g_sum[c] * inv_n;
        double v = g_sqs[c] * inv_n - m * m;
        float rstd = (float)rsqrt(v + 1e-5);
        float sc = __ldg(g + c) * rstd;
        g_scale[c] = sc;
        g_shift[c] = __ldg(b + c) - (float)m * sc;
    }
}

__global__ void bnrelu32_kernel(float* __restrict__ h, int total)
{
    int gid = blockIdx.x * blockDim.x + threadIdx.x;
    if (gid >= total) return;
    int c = gid & 31;
    float v = fmaf(h[gid], g_scale[c], g_shift[c]);
    h[gid] = v > 0.f ? v : 0.f;
}

// apply BN affine + relu to the raw k-max (valid because gamma=1 > 0: affine is
// monotonic, so max over k commutes with it)
__global__ void bnapply_kernel(const float* __restrict__ gmax, float* __restrict__ hout,
                               int total, int Cm1)
{
    int gid = blockIdx.x * blockDim.x + threadIdx.x;
    if (gid >= total) return;
    int c = gid & Cm1;
    float v = fmaf(gmax[gid], g_scale[c], g_shift[c]);
    hout[gid] = v > 0.f ? v : 0.f;
}

// ---------------- FPS v2: one barrier/iter ----------------
template<int N, int M, int T>
__global__ void __launch_bounds__(T) fps2_kernel(const float* __restrict__ p, int* __restrict__ out_idx)
{
    constexpr int P = N / T;
    constexpr int NW = T / 32;
    int b = blockIdx.x;
    const float* pb = p + (long long)b * N * 3;
    int tid = threadIdx.x, lane = tid & 31, w = tid >> 5;

    float px[P], py[P], pz[P], md[P];
#pragma unroll
    for (int i = 0; i < P; i++) {
        int n = tid + i * T;
        px[i] = __ldg(pb + 3*n); py[i] = __ldg(pb + 3*n + 1); pz[i] = __ldg(pb + 3*n + 2);
        md[i] = 3.4e38f;
    }

    __shared__ unsigned sv[2][NW];
    __shared__ unsigned si[2][NW];
    int last = 0;

    for (int m = 0; m < M; m++) {
        if (tid == 0) out_idx[b*M + m] = last;
        float lx = __ldg(pb + 3*last);
        float ly = __ldg(pb + 3*last + 1);
        float lz = __ldg(pb + 3*last + 2);

        float bestv = -1.0f; unsigned besti = 0;
#pragma unroll
        for (int i = 0; i < P; i++) {
            float dx = px[i] - lx, dy = py[i] - ly, dz = pz[i] - lz;
            float d = fmaf(dx, dx, fmaf(dy, dy, dz*dz));
            float mi = fminf(md[i], d);
            md[i] = mi;
            if (mi > bestv) { bestv = mi; besti = (unsigned)(tid + i*T); }
        }
        unsigned fb = __float_as_uint(bestv);
        unsigned wmax = __reduce_max_sync(0xffffffffu, fb);
        unsigned cand = (fb == wmax) ? besti : 0xffffffffu;
        unsigned widx = __reduce_min_sync(0xffffffffu, cand);
        int buf = m & 1;
        if (lane == 0) { sv[buf][w] = wmax; si[buf][w] = widx; }
        __syncthreads();
        unsigned vv = (lane < NW) ? sv[buf][lane] : 0u;
        unsigned ii = (lane < NW) ? si[buf][lane] : 0xffffffffu;
        unsigned m2 = __reduce_max_sync(0xffffffffu, vv);
        unsigned c2 = (vv == m2) ? ii : 0xffffffffu;
        last = (int)__reduce_min_sync(0xffffffffu, c2);
        // next write to sv[buf] is at iter m+2, after barrier m+1 -> race-free
    }
}

// ---------------- gather points ----------------
__global__ void gather_p_kernel(const float* __restrict__ p_in, const int* __restrict__ idx,
                                float* __restrict__ p_out, int N, int M)
{
    int gid = blockIdx.x * blockDim.x + threadIdx.x;
    if (gid >= BB * M * 3) return;
    int c = gid % 3;
    int m = (gid / 3) % M;
    int b = gid / (3 * M);
    p_out[gid] = p_in[((long long)b * N + idx[b*M + m]) * 3 + c];
}

// ---------------- kNN ----------------
#define KNN_TRY(PX,PY,PZ,NI) {                                                 \
    float dx = (PX) - qx, dy = (PY) - qy, dz = (PZ) - qz;                      \
    float d = fmaf(dx, dx, fmaf(dy, dy, dz*dz));                               \
    if (d < kd[15]) {                                                          \
        kd[15] = d; ki[15] = (NI);                                             \
        _Pragma("unroll")                                                      \
        for (int j = 15; j > 0; --j) {                                         \
            if (kd[j] < kd[j-1]) {                                             \
                float td = kd[j]; kd[j] = kd[j-1]; kd[j-1] = td;               \
                int   ti = ki[j]; ki[j] = ki[j-1]; ki[j-1] = ti;               \
            }                                                                  \
        }                                                                      \
    } }

template<int N, int QB>
__global__ void __launch_bounds__(QB) knn_kernel(const float* __restrict__ p,
                                                 const float* __restrict__ q,
                                                 int M, int* __restrict__ nidx)
{
    extern __shared__ float sm[];
    float* sx = sm; float* sy = sm + N; float* sz = sm + 2*N;
    int bpb = M / QB;
    int b  = blockIdx.x / bpb;
    int q0 = (blockIdx.x % bpb) * QB;
    const float* pb = p + (long long)b * N * 3;
    for (int i = threadIdx.x; i < N; i += QB) {
        sx[i] = pb[3*i]; sy[i] = pb[3*i+1]; sz[i] = pb[3*i+2];
    }
    __syncthreads();

    int qi = q0 + threadIdx.x;
    const float* qp = q + ((long long)b * M + qi) * 3;
    float qx = qp[0], qy = qp[1], qz = qp[2];

    float kd[16]; int ki[16];
#pragma unroll
    for (int i = 0; i < 16; i++) { kd[i] = 3.4e38f; ki[i] = 0; }

    for (int n0 = 0; n0 < N; n0 += 4) {
        float4 X = *reinterpret_cast<const float4*>(sx + n0);
        float4 Y = *reinterpret_cast<const float4*>(sy + n0);
        float4 Z = *reinterpret_cast<const float4*>(sz + n0);
        KNN_TRY(X.x, Y.x, Z.x, n0 + 0);
        KNN_TRY(X.y, Y.y, Z.y, n0 + 1);
        KNN_TRY(X.z, Y.z, Z.z, n0 + 2);
        KNN_TRY(X.w, Y.w, Z.w, n0 + 3);
    }
    int base = ((long long)b * M + qi) * 16;
#pragma unroll
    for (int j = 0; j < 16; j++) nidx[base + j] = ki[j];
}

// ---------------- fused GEMM: gather-A + W, epilogue = col-stats + max over k ----------------
// virtual A[row][c]: row=(b,m,k) -> n=nidx[row]; c<3: p[n]-newp[b,m]; else h[n][c-3]
__global__ void __launch_bounds__(256) gemmF_kernel(
    const float* __restrict__ p_in, const float* __restrict__ h_in,
    const float* __restrict__ newp, const int* __restrict__ nidx,
    const float* __restrict__ W, float* __restrict__ gmax,
    int N, int M, int Cin, int COUT)
{
    int CK = Cin + 3;
    __shared__ float As[16][68];
    __shared__ float Bs[16][68];
    __shared__ int sH[64], sP[64], sQ[64];
    int t = threadIdx.x;
    int row0 = blockIdx.x * 64;
    int col0 = blockIdx.y * 64;
    int tx = t & 15, ty = t >> 4;

    if (t < 64) {
        int r  = row0 + t;
        int n  = nidx[r];
        int bm = r >> 4;
        int b  = bm / M;
        sH[t] = (b * N + n) * Cin;
        sP[t] = (b * N + n) * 3;
        sQ[t] = bm * 3;
    }
    __syncthreads();

    float acc[4][4];
#pragma unroll
    for (int i = 0; i < 4; i++)
#pragma unroll
        for (int j = 0; j < 4; j++) acc[i][j] = 0.f;

    for (int k0 = 0; k0 < CK; k0 += 16) {
#pragma unroll
        for (int j = 0; j < 4; j++) {
            int lin = t + j * 256;
            int i = lin >> 4, kk = lin & 15;
            int c = k0 + kk;
            float v = 0.f;
            if (c < CK) {
                if (c < 3) v = __ldg(p_in + sP[i] + c) - __ldg(newp + sQ[i] + c);
                else       v = __ldg(h_in + sH[i] + c - 3);
            }
            As[kk][i] = v;
        }
#pragma unroll
        for (int j = 0; j < 4; j++) {
            int lin = t + j * 256;
            int kk = lin >> 6, cc = lin & 63;
            Bs[kk][cc] = (k0 + kk < CK) ? __ldg(W + (long long)(k0 + kk) * COUT + col0 + cc) : 0.f;
        }
        __syncthreads();
#pragma unroll
        for (int kk = 0; kk < 16; kk++) {
            float a0 = As[kk][ty*4+0], a1 = As[kk][ty*4+1], a2 = As[kk][ty*4+2], a3 = As[kk][ty*4+3];
            float b0 = Bs[kk][tx*4+0], b1 = Bs[kk][tx*4+1], b2 = Bs[kk][tx*4+2], b3 = Bs[kk][tx*4+3];
            acc[0][0]=fmaf(a0,b0,acc[0][0]); acc[0][1]=fmaf(a0,b1,acc[0][1]);
            acc[0][2]=fmaf(a0,b2,acc[0][2]); acc[0][3]=fmaf(a0,b3,acc[0][3]);
            acc[1][0]=fmaf(a1,b0,acc[1][0]); acc[1][1]=fmaf(a1,b1,acc[1][1]);
            acc[1][2]=fmaf(a1,b2,acc[1][2]); acc[1][3]=fmaf(a1,b3,acc[1][3]);
            acc[2][0]=fmaf(a2,b0,acc[2][0]); acc[2][1]=fmaf(a2,b1,acc[2][1]);
            acc[2][2]=fmaf(a2,b2,acc[2][2]); acc[2][3]=fmaf(a2,b3,acc[2][3]);
            acc[3][0]=fmaf(a3,b0,acc[3][0]); acc[3][1]=fmaf(a3,b1,acc[3][1]);
            acc[3][2]=fmaf(a3,b2,acc[3][2]); acc[3][3]=fmaf(a3,b3,acc[3][3]);
        }
        __syncthreads();
    }

    // ---- epilogue: per-column sum/sumsq (for BN stats) + max over 16-row groups ----
    float cs[4], cq[4], cm[4];
#pragma unroll
    for (int j = 0; j < 4; j++) {
        cs[j] = acc[0][j] + acc[1][j] + acc[2][j] + acc[3][j];
        cq[j] = acc[0][j]*acc[0][j] + acc[1][j]*acc[1][j] + acc[2][j]*acc[2][j] + acc[3][j]*acc[3][j];
        cm[j] = fmaxf(fmaxf(acc[0][j], acc[1][j]), fmaxf(acc[2][j], acc[3][j]));
    }
#pragma unroll
    for (int j = 0; j < 4; j++) { As[ty][tx*4+j] = cs[j]; Bs[ty][tx*4+j] = cq[j]; }
    __syncthreads();
    if (t < 64) {
        double s = 0.0, q = 0.0;
#pragma unroll
        for (int r = 0; r < 16; r++) { s += (double)As[r][t]; q += (double)Bs[r][t]; }
        atomicAdd(&g_sum[col0 + t], s);
        atomicAdd(&g_sqs[col0 + t], q);
    }
    __syncthreads();
#pragma unroll
    for (int j = 0; j < 4; j++) As[ty][tx*4+j] = cm[j];
    __syncthreads();
    {
        int grp = t >> 6, col = t & 63;   // 4 groups of 16 rows, 64 cols
        float mm = fmaxf(fmaxf(As[grp*4+0][col], As[grp*4+1][col]),
                         fmaxf(As[grp*4+2][col], As[grp*4+3][col]));
        gmax[(long long)((row0 >> 4) + grp) * COUT + col0 + col] = mm;
    }
}

// ---------------- mean pool ----------------
__global__ void mean_kernel(const float* __restrict__ h4)
{
    int gid = blockIdx.x * blockDim.x + threadIdx.x;
    if (gid >= BB * 512) return;
    int c = gid & 511, b = gid >> 9;
    float s = 0.f;
#pragma unroll
    for (int k = 0; k < 16; k++) s += h4[((long long)b * 16 + k) * 512 + c];
    g_z[gid] = s * (1.f / 16.f);
}

// ---------------- classifier head ----------------
__global__ void head_kernel(const float* __restrict__ in, const float* __restrict__ W,
                            const float* __restrict__ bias,
                            const float* __restrict__ gg, const float* __restrict__ bb,
                            float* __restrict__ outp, int Cin, int Cout, int bn_relu)
{
    int j = blockIdx.x * blockDim.x + threadIdx.x;
    if (j >= Cout) return;
    float acc[16];
    float bs = __ldg(bias + j);
#pragma unroll
    for (int b = 0; b < 16; b++) acc[b] = bs;
    for (int c = 0; c < Cin; c++) {
        float w = __ldg(W + (long long)c * Cout + j);
#pragma unroll
        for (int b = 0; b < 16; b++) acc[b] = fmaf(in[b*Cin + c], w, acc[b]);
    }
    if (bn_relu) {
        float s = 0.f;
#pragma unroll
        for (int b = 0; b < 16; b++) s += acc[b];
        float m = s * (1.f/16.f);
        float v = 0.f;
#pragma unroll
        for (int b = 0; b < 16; b++) { float d = acc[b] - m; v = fmaf(d, d, v); }
        v *= (1.f/16.f);
        float sc = __ldg(gg + j) * rsqrtf(v + 1e-5f);
        float sh = __ldg(bb + j) - m * sc;
#pragma unroll
        for (int b = 0; b < 16; b++) {
            float o = fmaf(acc[b], sc, sh);
            outp[b*Cout + j] = o > 0.f ? o : 0.f;
        }
    } else {
#pragma unroll
        for (int b = 0; b < 16; b++) outp[b*Cout + j] = acc[b];
    }
}

// ---------------- host launchers ----------------
static void run_fps(const float* p, int* idx, int N)
{
    if      (N == 4096) fps2_kernel<4096,1024,512><<<BB,512>>>(p, idx);
    else if (N == 1024) fps2_kernel<1024, 256,512><<<BB,512>>>(p, idx);
    else if (N ==  256) fps2_kernel< 256,  64,256><<<BB,256>>>(p, idx);
    else                fps2_kernel<  64,  16, 64><<<BB, 64>>>(p, idx);
}

static void run_knn(const float* p, const float* q, int N, int M, int* nidx)
{
    if      (N == 4096) knn_kernel<4096,128><<<BB*(M/128),128,3*4096*4>>>(p, q, M, nidx);
    else if (N == 1024) knn_kernel<1024, 64><<<BB*(M/ 64), 64,3*1024*4>>>(p, q, M, nidx);
    else if (N ==  256) knn_kernel< 256, 64><<<BB*(M/ 64), 64,3* 256*4>>>(p, q, M, nidx);
    else                knn_kernel<  64, 16><<<BB*(M/ 16), 16,3*  64*4>>>(p, q, M, nidx);
}

static void run_stage(const float* p_in, const float* h_in, float* p_out, float* h_out,
                      int N, int M, int Cin, int Cout,
                      const float* W, const float* g, const float* b,
                      int* idx, int* nidx, float* gmax)
{
    run_fps(p_in, idx, N);
    int t3 = BB * M * 3;
    gather_p_kernel<<<(t3+255)/256,256>>>(p_in, idx, p_out, N, M);
    run_knn(p_in, p_out, N, M, nidx);
    int rows = BB * M * 16;
    zero_stats_kernel<<<1,512>>>();
    dim3 gg(rows/64, Cout/64);
    gemmF_kernel<<<gg, 256>>>(p_in, h_in, p_out, nidx, W, gmax, N, M, Cin, Cout);
    finalize_bn_kernel<<<1,512>>>(g, b, Cout, 1.0/(double)rows);
    int bm = BB * M;
    bnapply_kernel<<<(bm*Cout+255)/256,256>>>(gmax, h_out, bm*Cout, Cout-1);
}

extern "C" void kernel_launch(void* const* d_in, const int* in_sizes, int n_in,
                              void* d_out, int out_size)
{
    const float* x   = (const float*)d_in[0];
    const float* W1  = (const float*)d_in[1];
    const float* g1  = (const float*)d_in[2];
    const float* b1  = (const float*)d_in[3];
    const float* W2  = (const float*)d_in[4];
    const float* g2  = (const float*)d_in[5];
    const float* b2  = (const float*)d_in[6];
    const float* W3  = (const float*)d_in[7];
    const float* g3  = (const float*)d_in[8];
    const float* b3  = (const float*)d_in[9];
    const float* W4  = (const float*)d_in[10];
    const float* g4  = (const float*)d_in[11];
    const float* b4  = (const float*)d_in[12];
    const float* W5  = (const float*)d_in[13];
    const float* g5  = (const float*)d_in[14];
    const float* b5  = (const float*)d_in[15];
    const float* Wc1 = (const float*)d_in[16];
    const float* bc1 = (const float*)d_in[17];
    const float* gc1 = (const float*)d_in[18];
    const float* hc1 = (const float*)d_in[19];
    const float* Wc2 = (const float*)d_in[20];
    const float* bc2 = (const float*)d_in[21];
    const float* gc2 = (const float*)d_in[22];
    const float* hc2 = (const float*)d_in[23];
    const float* Wc3 = (const float*)d_in[24];
    const float* bc3 = (const float*)d_in[25];
    float* out = (float*)d_out;

    float *h0, *h1, *h2, *h3, *h4, *p1, *p2, *p3, *p4, *gmax, *z, *t1, *t2;
    int *idx, *nidx;
    cudaGetSymbolAddress((void**)&h0,   g_h0);
    cudaGetSymbolAddress((void**)&h1,   g_h1);
    cudaGetSymbolAddress((void**)&h2,   g_h2);
    cudaGetSymbolAddress((void**)&h3,   g_h3);
    cudaGetSymbolAddress((void**)&h4,   g_h4);
    cudaGetSymbolAddress((void**)&p1,   g_p1);
    cudaGetSymbolAddress((void**)&p2,   g_p2);
    cudaGetSymbolAddress((void**)&p3,   g_p3);
    cudaGetSymbolAddress((void**)&p4,   g_p4);
    cudaGetSymbolAddress((void**)&gmax, g_gmax);
    cudaGetSymbolAddress((void**)&z,    g_z);
    cudaGetSymbolAddress((void**)&t1,   g_t1);
    cudaGetSymbolAddress((void**)&t2,   g_t2);
    cudaGetSymbolAddress((void**)&idx,  g_idx);
    cudaGetSymbolAddress((void**)&nidx, g_nidx);

    // stage 0: h0 = relu(BN(x @ W1))
    int tot0 = BB*4096*32;
    lin0_kernel<<<(tot0+255)/256,256>>>(x, W1, h0);
    zero_stats_kernel<<<1,512>>>();
    { dim3 sb(32, 32); stats_kernel<<<128, sb>>>(h0, BB*4096, 32); }
    finalize_bn_kernel<<<1,512>>>(g1, b1, 32, 1.0/(double)(BB*4096));
    bnrelu32_kernel<<<(tot0+255)/256,256>>>(h0, tot0);

    // transition-down stages (feat-gather + stats + maxpool fused into GEMM)
    run_stage(x,  h0, p1, h1, 4096, 1024,  32,  64, W2, g2, b2, idx, nidx, gmax);
    run_stage(p1, h1, p2, h2, 1024,  256,  64, 128, W3, g3, b3, idx, nidx, gmax);
    run_stage(p2, h2, p3, h3,  256,   64, 128, 256, W4, g4, b4, idx, nidx, gmax);
    run_stage(p3, h3, p4, h4,   64,   16, 256, 512, W5, g5, b5, idx, nidx, gmax);

    // mean pool + head
    mean_kernel<<<(BB*512+255)/256,256>>>(h4);
    head_kernel<<<1,256>>>(z,  Wc1, bc1, gc1, hc1, t1, 512, 256, 1);
    head_kernel<<<1,128>>>(t1, Wc2, bc2, gc2, hc2, t2, 256, 128, 1);
    head_kernel<<<1, 64>>>(t2, Wc3, bc3, (const float*)0, (const float*)0, out, 128, 40, 0);
}

// round 8
// speedup vs baseline: 1.7463x; 1.1925x over previous
#include <cuda_runtime.h>
#include <cuda_bf16.h>
#include <math.h>

#define BB 16

// ---------------- scratch ----------------
__device__ float  g_h0[BB*4096*32];
__device__ float  g_h1[BB*1024*64];
__device__ float  g_h2[BB*256*128];
__device__ float  g_h3[BB*64*256];
__device__ float  g_h4[BB*16*512];
__device__ float  g_p1[BB*1024*3];
__device__ float  g_p2[BB*256*3];
__device__ float  g_p3[BB*64*3];
__device__ float  g_p4[BB*16*3];
__device__ int    g_idx[BB*1024];
__device__ int    g_nidx[BB*1024*16];
__device__ float  g_gmax[BB*1024*64];
__device__ double g_sum[512], g_sqs[512];
__device__ float  g_scale[512], g_shift[512];
__device__ float  g_z[BB*512];
__device__ float  g_t1[BB*256];
__device__ float  g_t2[BB*128];

// ---------------- stage 0 linear ----------------
__global__ void lin0_kernel(const float* __restrict__ x, const float* __restrict__ W1,
                            float* __restrict__ h)
{
    int gid = blockIdx.x * blockDim.x + threadIdx.x;
    if (gid >= BB*4096*32) return;
    int d = gid & 31, r = gid >> 5;
    float v =        __ldg(x + r*3 + 0) * __ldg(W1 + d);
    v = fmaf(__ldg(x + r*3 + 1), __ldg(W1 + 32 + d), v);
    v = fmaf(__ldg(x + r*3 + 2), __ldg(W1 + 64 + d), v);
    h[gid] = v;
}

// ---------------- BN statistics ----------------
__global__ void zero_stats_kernel()
{
    int i = threadIdx.x;
    if (i < 512) { g_sum[i] = 0.0; g_sqs[i] = 0.0; }
}

__global__ void stats_kernel(const float* __restrict__ y, int nrows, int C)
{
    int c  = threadIdx.x;
    int r0 = blockIdx.x * blockDim.y + threadIdx.y;
    int stride = gridDim.x * blockDim.y;
    double s = 0.0, q = 0.0;
    for (int r = r0; r < nrows; r += stride) {
        float v = y[(long long)r * C + c];
        s += (double)v;
        q += (double)v * (double)v;
    }
    atomicAdd(&g_sum[c], s);
    atomicAdd(&g_sqs[c], q);
}

__global__ void finalize_bn_kernel(const float* __restrict__ g, const float* __restrict__ b,
                                   int C, double inv_n)
{
    int c = threadIdx.x;
    if (c < C) {
        double m = g_sum[c] * inv_n;
        double v = g_sqs[c] * inv_n - m * m;
        float rstd = (float)rsqrt(v + 1e-5);
        float sc = __ldg(g + c) * rstd;
        g_scale[c] = sc;
        g_shift[c] = __ldg(b + c) - (float)m * sc;
    }
}

__global__ void bnrelu32_kernel(float* __restrict__ h, int total)
{
    int gid = blockIdx.x * blockDim.x + threadIdx.x;
    if (gid >= total) return;
    int c = gid & 31;
    float v = fmaf(h[gid], g_scale[c], g_shift[c]);
    h[gid] = v > 0.f ? v : 0.f;
}

__global__ void bnapply_kernel(const float* __restrict__ gmax, float* __restrict__ hout,
                               int total, int Cm1)
{
    int gid = blockIdx.x * blockDim.x + threadIdx.x;
    if (gid >= total) return;
    int c = gid & Cm1;
    float v = fmaf(gmax[gid], g_scale[c], g_shift[c]);
    hout[gid] = v > 0.f ? v : 0.f;
}

// ---------------- FPS v2: one barrier/iter ----------------
template<int N, int M, int T>
__global__ void __launch_bounds__(T) fps2_kernel(const float* __restrict__ p, int* __restrict__ out_idx)
{
    constexpr int P = N / T;
    constexpr int NW = T / 32;
    int b = blockIdx.x;
    const float* pb = p + (long long)b * N * 3;
    int tid = threadIdx.x, lane = tid & 31, w = tid >> 5;

    float px[P], py[P], pz[P], md[P];
#pragma unroll
    for (int i = 0; i < P; i++) {
        int n = tid + i * T;
        px[i] = __ldg(pb + 3*n); py[i] = __ldg(pb + 3*n + 1); pz[i] = __ldg(pb + 3*n + 2);
        md[i] = 3.4e38f;
    }

    __shared__ unsigned sv[2][NW];
    __shared__ unsigned si[2][NW];
    int last = 0;

    for (int m = 0; m < M; m++) {
        if (tid == 0) out_idx[b*M + m] = last;
        float lx = __ldg(pb + 3*last);
        float ly = __ldg(pb + 3*last + 1);
        float lz = __ldg(pb + 3*last + 2);

        float bestv = -1.0f; unsigned besti = 0;
#pragma unroll
        for (int i = 0; i < P; i++) {
            float dx = px[i] - lx, dy = py[i] - ly, dz = pz[i] - lz;
            float d = fmaf(dx, dx, fmaf(dy, dy, dz*dz));
            float mi = fminf(md[i], d);
            md[i] = mi;
            if (mi > bestv) { bestv = mi; besti = (unsigned)(tid + i*T); }
        }
        unsigned fb = __float_as_uint(bestv);
        unsigned wmax = __reduce_max_sync(0xffffffffu, fb);
        unsigned cand = (fb == wmax) ? besti : 0xffffffffu;
        unsigned widx = __reduce_min_sync(0xffffffffu, cand);
        int buf = m & 1;
        if (lane == 0) { sv[buf][w] = wmax; si[buf][w] = widx; }
        __syncthreads();
        unsigned vv = (lane < NW) ? sv[buf][lane] : 0u;
        unsigned ii = (lane < NW) ? si[buf][lane] : 0xffffffffu;
        unsigned m2 = __reduce_max_sync(0xffffffffu, vv);
        unsigned c2 = (vv == m2) ? ii : 0xffffffffu;
        last = (int)__reduce_min_sync(0xffffffffu, c2);
    }
}

// ---------------- gather points ----------------
__global__ void gather_p_kernel(const float* __restrict__ p_in, const int* __restrict__ idx,
                                float* __restrict__ p_out, int N, int M)
{
    int gid = blockIdx.x * blockDim.x + threadIdx.x;
    if (gid >= BB * M * 3) return;
    int c = gid % 3;
    int m = (gid / 3) % M;
    int b = gid / (3 * M);
    p_out[gid] = p_in[((long long)b * N + idx[b*M + m]) * 3 + c];
}

// ---------------- kNN with split-k candidate scan ----------------
#define KNN_TRY(PX,PY,PZ,NI) {                                                 \
    float dx = (PX) - qx, dy = (PY) - qy, dz = (PZ) - qz;                      \
    float d = fmaf(dx, dx, fmaf(dy, dy, dz*dz));                               \
    if (d < kd[15]) {                                                          \
        kd[15] = d; ki[15] = (NI);                                             \
        _Pragma("unroll")                                                      \
        for (int j = 15; j > 0; --j) {                                         \
            if (kd[j] < kd[j-1]) {                                             \
                float td = kd[j]; kd[j] = kd[j-1]; kd[j-1] = td;               \
                int   ti = ki[j]; ki[j] = ki[j-1]; ki[j-1] = ti;               \
            }                                                                  \
        }                                                                      \
    } }

// SPLIT threads per query; part ranges are index-contiguous so a sequential
// strict-< merge over parts reproduces full index-order insertion exactly.
template<int N, int QB, int SPLIT>
__global__ void __launch_bounds__(QB*SPLIT) knn_split_kernel(const float* __restrict__ p,
                                                             const float* __restrict__ q,
                                                             int M, int* __restrict__ nidx)
{
    constexpr int T = QB * SPLIT;
    constexpr int CHUNK = N / SPLIT;
    constexpr int CSTR = 16 * SPLIT + 1;   // padded stride (65) -> conflict-free
    extern __shared__ float sm[];
    float* sx = sm; float* sy = sm + N; float* sz = sm + 2*N;
    float* cd = sm + 3*N;                  // QB * CSTR floats
    int*   ci = (int*)(cd + QB*CSTR);      // QB * CSTR ints

    int tid = threadIdx.x;
    int bpb = M / QB;
    int b  = blockIdx.x / bpb;
    int q0 = (blockIdx.x % bpb) * QB;
    const float* pb = p + (long long)b * N * 3;
    for (int i = tid; i < N; i += T) {
        sx[i] = pb[3*i]; sy[i] = pb[3*i+1]; sz[i] = pb[3*i+2];
    }
    __syncthreads();

    int qi   = tid % QB;
    int part = tid / QB;
    const float* qp = q + ((long long)b * M + q0 + qi) * 3;
    float qx = qp[0], qy = qp[1], qz = qp[2];

    float kd[16]; int ki[16];
#pragma unroll
    for (int i = 0; i < 16; i++) { kd[i] = 3.4e38f; ki[i] = 0; }

    int n_lo = part * CHUNK;
    for (int n0 = n_lo; n0 < n_lo + CHUNK; n0 += 4) {
        float4 X = *reinterpret_cast<const float4*>(sx + n0);
        float4 Y = *reinterpret_cast<const float4*>(sy + n0);
        float4 Z = *reinterpret_cast<const float4*>(sz + n0);
        KNN_TRY(X.x, Y.x, Z.x, n0 + 0);
        KNN_TRY(X.y, Y.y, Z.y, n0 + 1);
        KNN_TRY(X.z, Y.z, Z.z, n0 + 2);
        KNN_TRY(X.w, Y.w, Z.w, n0 + 3);
    }
    {
        float* d0 = cd + qi * CSTR + part * 16;
        int*   i0 = ci + qi * CSTR + part * 16;
#pragma unroll
        for (int j = 0; j < 16; j++) { d0[j] = kd[j]; i0[j] = ki[j]; }
    }
    __syncthreads();

    if (part == 0) {
        float md[16]; int mi[16];
#pragma unroll
        for (int i = 0; i < 16; i++) { md[i] = 3.4e38f; mi[i] = 0; }
        const float* d0 = cd + qi * CSTR;
        const int*   i0 = ci + qi * CSTR;
        for (int s = 0; s < 16 * SPLIT; s++) {
            float d = d0[s];
            if (d < md[15]) {
                md[15] = d; mi[15] = i0[s];
#pragma unroll
                for (int j = 15; j > 0; --j) {
                    if (md[j] < md[j-1]) {
                        float td = md[j]; md[j] = md[j-1]; md[j-1] = td;
                        int   ti = mi[j]; mi[j] = mi[j-1]; mi[j-1] = ti;
                    }
                }
            }
        }
        int base = ((long long)b * M + q0 + qi) * 16;
#pragma unroll
        for (int j = 0; j < 16; j++) nidx[base + j] = mi[j];
    }
}

// ---------------- fused GEMM: gather-A + W, epilogue = col-stats + max over k ----------------
__global__ void __launch_bounds__(256) gemmF_kernel(
    const float* __restrict__ p_in, const float* __restrict__ h_in,
    const float* __restrict__ newp, const int* __restrict__ nidx,
    const float* __restrict__ W, float* __restrict__ gmax,
    int N, int M, int Cin, int COUT)
{
    int CK = Cin + 3;
    __shared__ float As[16][68];
    __shared__ float Bs[16][68];
    __shared__ int sH[64], sP[64], sQ[64];
    int t = threadIdx.x;
    int row0 = blockIdx.x * 64;
    int col0 = blockIdx.y * 64;
    int tx = t & 15, ty = t >> 4;

    if (t < 64) {
        int r  = row0 + t;
        int n  = nidx[r];
        int bm = r >> 4;
        int b  = bm / M;
        sH[t] = (b * N + n) * Cin;
        sP[t] = (b * N + n) * 3;
        sQ[t] = bm * 3;
    }
    __syncthreads();

    float acc[4][4];
#pragma unroll
    for (int i = 0; i < 4; i++)
#pragma unroll
        for (int j = 0; j < 4; j++) acc[i][j] = 0.f;

    for (int k0 = 0; k0 < CK; k0 += 16) {
#pragma unroll
        for (int j = 0; j < 4; j++) {
            int lin = t + j * 256;
            int i = lin >> 4, kk = lin & 15;
            int c = k0 + kk;
            float v = 0.f;
            if (c < CK) {
                if (c < 3) v = __ldg(p_in + sP[i] + c) - __ldg(newp + sQ[i] + c);
                else       v = __ldg(h_in + sH[i] + c - 3);
            }
            As[kk][i] = v;
        }
#pragma unroll
        for (int j = 0; j < 4; j++) {
            int lin = t + j * 256;
            int kk = lin >> 6, cc = lin & 63;
            Bs[kk][cc] = (k0 + kk < CK) ? __ldg(W + (long long)(k0 + kk) * COUT + col0 + cc) : 0.f;
        }
        __syncthreads();
#pragma unroll
        for (int kk = 0; kk < 16; kk++) {
            float a0 = As[kk][ty*4+0], a1 = As[kk][ty*4+1], a2 = As[kk][ty*4+2], a3 = As[kk][ty*4+3];
            float b0 = Bs[kk][tx*4+0], b1 = Bs[kk][tx*4+1], b2 = Bs[kk][tx*4+2], b3 = Bs[kk][tx*4+3];
            acc[0][0]=fmaf(a0,b0,acc[0][0]); acc[0][1]=fmaf(a0,b1,acc[0][1]);
            acc[0][2]=fmaf(a0,b2,acc[0][2]); acc[0][3]=fmaf(a0,b3,acc[0][3]);
            acc[1][0]=fmaf(a1,b0,acc[1][0]); acc[1][1]=fmaf(a1,b1,acc[1][1]);
            acc[1][2]=fmaf(a1,b2,acc[1][2]); acc[1][3]=fmaf(a1,b3,acc[1][3]);
            acc[2][0]=fmaf(a2,b0,acc[2][0]); acc[2][1]=fmaf(a2,b1,acc[2][1]);
            acc[2][2]=fmaf(a2,b2,acc[2][2]); acc[2][3]=fmaf(a2,b3,acc[2][3]);
            acc[3][0]=fmaf(a3,b0,acc[3][0]); acc[3][1]=fmaf(a3,b1,acc[3][1]);
            acc[3][2]=fmaf(a3,b2,acc[3][2]); acc[3][3]=fmaf(a3,b3,acc[3][3]);
        }
        __syncthreads();
    }

    float cs[4], cq[4], cm[4];
#pragma unroll
    for (int j = 0; j < 4; j++) {
        cs[j] = acc[0][j] + acc[1][j] + acc[2][j] + acc[3][j];
        cq[j] = acc[0][j]*acc[0][j] + acc[1][j]*acc[1][j] + acc[2][j]*acc[2][j] + acc[3][j]*acc[3][j];
        cm[j] = fmaxf(fmaxf(acc[0][j], acc[1][j]), fmaxf(acc[2][j], acc[3][j]));
    }
#pragma unroll
    for (int j = 0; j < 4; j++) { As[ty][tx*4+j] = cs[j]; Bs[ty][tx*4+j] = cq[j]; }
    __syncthreads();
    if (t < 64) {
        double s = 0.0, q = 0.0;
#pragma unroll
        for (int r = 0; r < 16; r++) { s += (double)As[r][t]; q += (double)Bs[r][t]; }
        atomicAdd(&g_sum[col0 + t], s);
        atomicAdd(&g_sqs[col0 + t], q);
    }
    __syncthreads();
#pragma unroll
    for (int j = 0; j < 4; j++) As[ty][tx*4+j] = cm[j];
    __syncthreads();
    {
        int grp = t >> 6, col = t & 63;
        float mm = fmaxf(fmaxf(As[grp*4+0][col], As[grp*4+1][col]),
                         fmaxf(As[grp*4+2][col], As[grp*4+3][col]));
        gmax[(long long)((row0 >> 4) + grp) * COUT + col0 + col] = mm;
    }
}

// ---------------- mean pool ----------------
__global__ void mean_kernel(const float* __restrict__ h4)
{
    int gid = blockIdx.x * blockDim.x + threadIdx.x;
    if (gid >= BB * 512) return;
    int c = gid & 511, b = gid >> 9;
    float s = 0.f;
#pragma unroll
    for (int k = 0; k < 16; k++) s += h4[((long long)b * 16 + k) * 512 + c];
    g_z[gid] = s * (1.f / 16.f);
}

// ---------------- classifier head (activations cached in smem) ----------------
__global__ void head_kernel(const float* __restrict__ in, const float* __restrict__ W,
                            const float* __restrict__ bias,
                            const float* __restrict__ gg, const float* __restrict__ bb,
                            float* __restrict__ outp, int Cin, int Cout, int bn_relu)
{
    __shared__ float s_in[16*512];
    int tid = threadIdx.x;
    for (int i = tid; i < 16*Cin; i += blockDim.x) s_in[i] = in[i];
    __syncthreads();

    int j = blockIdx.x * blockDim.x + tid;
    if (j >= Cout) return;
    float acc[16];
    float bs = __ldg(bias + j);
#pragma unroll
    for (int b = 0; b < 16; b++) acc[b] = bs;
    for (int c = 0; c < Cin; c++) {
        float w = __ldg(W + (long long)c * Cout + j);
#pragma unroll
        for (int b = 0; b < 16; b++) acc[b] = fmaf(s_in[b*Cin + c], w, acc[b]);
    }
    if (bn_relu) {
        float s = 0.f;
#pragma unroll
        for (int b = 0; b < 16; b++) s += acc[b];
        float m = s * (1.f/16.f);
        float v = 0.f;
#pragma unroll
        for (int b = 0; b < 16; b++) { float d = acc[b] - m; v = fmaf(d, d, v); }
        v *= (1.f/16.f);
        float sc = __ldg(gg + j) * rsqrtf(v + 1e-5f);
        float sh = __ldg(bb + j) - m * sc;
#pragma unroll
        for (int b = 0; b < 16; b++) {
            float o = fmaf(acc[b], sc, sh);
            outp[b*Cout + j] = o > 0.f ? o : 0.f;
        }
    } else {
#pragma unroll
        for (int b = 0; b < 16; b++) outp[b*Cout + j] = acc[b];
    }
}

// ---------------- host launchers ----------------
static void run_fps(const float* p, int* idx, int N)
{
    if      (N == 4096) fps2_kernel<4096,1024,512><<<BB,512>>>(p, idx);
    else if (N == 1024) fps2_kernel<1024, 256,512><<<BB,512>>>(p, idx);
    else if (N ==  256) fps2_kernel< 256,  64,256><<<BB,256>>>(p, idx);
    else                fps2_kernel<  64,  16, 64><<<BB, 64>>>(p, idx);
}

static void run_knn(const float* p, const float* q, int N, int M, int* nidx)
{
    if (N == 4096) {
        constexpr int QB = 64, SP = 4;
        size_t smem = 3*4096*4 + (size_t)QB*(16*SP+1)*8;
        cudaFuncSetAttribute(knn_split_kernel<4096,QB,SP>,
                             cudaFuncAttributeMaxDynamicSharedMemorySize, (int)smem);
        knn_split_kernel<4096,QB,SP><<<BB*(M/QB), QB*SP, smem>>>(p, q, M, nidx);
    } else if (N == 1024) {
        constexpr int QB = 32, SP = 4;
        size_t smem = 3*1024*4 + (size_t)QB*(16*SP+1)*8;
        knn_split_kernel<1024,QB,SP><<<BB*(M/QB), QB*SP, smem>>>(p, q, M, nidx);
    } else if (N == 256) {
        constexpr int QB = 16, SP = 4;
        size_t smem = 3*256*4 + (size_t)QB*(16*SP+1)*8;
        knn_split_kernel<256,QB,SP><<<BB*(M/QB), QB*SP, smem>>>(p, q, M, nidx);
    } else {
        constexpr int QB = 16, SP = 4;
        size_t smem = 3*64*4 + (size_t)QB*(16*SP+1)*8;
        knn_split_kernel<64,QB,SP><<<BB*(M/QB), QB*SP, smem>>>(p, q, M, nidx);
    }
}

static void run_stage(const float* p_in, const float* h_in, float* p_out, float* h_out,
                      int N, int M, int Cin, int Cout,
                      const float* W, const float* g, const float* b,
                      int* idx, int* nidx, float* gmax)
{
    run_fps(p_in, idx, N);
    int t3 = BB * M * 3;
    gather_p_kernel<<<(t3+255)/256,256>>>(p_in, idx, p_out, N, M);
    run_knn(p_in, p_out, N, M, nidx);
    int rows = BB * M * 16;
    zero_stats_kernel<<<1,512>>>();
    dim3 gg(rows/64, Cout/64);
    gemmF_kernel<<<gg, 256>>>(p_in, h_in, p_out, nidx, W, gmax, N, M, Cin, Cout);
    finalize_bn_kernel<<<1,512>>>(g, b, Cout, 1.0/(double)rows);
    int bm = BB * M;
    bnapply_kernel<<<(bm*Cout+255)/256,256>>>(gmax, h_out, bm*Cout, Cout-1);
}

extern "C" void kernel_launch(void* const* d_in, const int* in_sizes, int n_in,
                              void* d_out, int out_size)
{
    const float* x   = (const float*)d_in[0];
    const float* W1  = (const float*)d_in[1];
    const float* g1  = (const float*)d_in[2];
    const float* b1  = (const float*)d_in[3];
    const float* W2  = (const float*)d_in[4];
    const float* g2  = (const float*)d_in[5];
    const float* b2  = (const float*)d_in[6];
    const float* W3  = (const float*)d_in[7];
    const float* g3  = (const float*)d_in[8];
    const float* b3  = (const float*)d_in[9];
    const float* W4  = (const float*)d_in[10];
    const float* g4  = (const float*)d_in[11];
    const float* b4  = (const float*)d_in[12];
    const float* W5  = (const float*)d_in[13];
    const float* g5  = (const float*)d_in[14];
    const float* b5  = (const float*)d_in[15];
    const float* Wc1 = (const float*)d_in[16];
    const float* bc1 = (const float*)d_in[17];
    const float* gc1 = (const float*)d_in[18];
    const float* hc1 = (const float*)d_in[19];
    const float* Wc2 = (const float*)d_in[20];
    const float* bc2 = (const float*)d_in[21];
    const float* gc2 = (const float*)d_in[22];
    const float* hc2 = (const float*)d_in[23];
    const float* Wc3 = (const float*)d_in[24];
    const float* bc3 = (const float*)d_in[25];
    float* out = (float*)d_out;

    float *h0, *h1, *h2, *h3, *h4, *p1, *p2, *p3, *p4, *gmax, *z, *t1, *t2;
    int *idx, *nidx;
    cudaGetSymbolAddress((void**)&h0,   g_h0);
    cudaGetSymbolAddress((void**)&h1,   g_h1);
    cudaGetSymbolAddress((void**)&h2,   g_h2);
    cudaGetSymbolAddress((void**)&h3,   g_h3);
    cudaGetSymbolAddress((void**)&h4,   g_h4);
    cudaGetSymbolAddress((void**)&p1,   g_p1);
    cudaGetSymbolAddress((void**)&p2,   g_p2);
    cudaGetSymbolAddress((void**)&p3,   g_p3);
    cudaGetSymbolAddress((void**)&p4,   g_p4);
    cudaGetSymbolAddress((void**)&gmax, g_gmax);
    cudaGetSymbolAddress((void**)&z,    g_z);
    cudaGetSymbolAddress((void**)&t1,   g_t1);
    cudaGetSymbolAddress((void**)&t2,   g_t2);
    cudaGetSymbolAddress((void**)&idx,  g_idx);
    cudaGetSymbolAddress((void**)&nidx, g_nidx);

    // stage 0
    int tot0 = BB*4096*32;
    lin0_kernel<<<(tot0+255)/256,256>>>(x, W1, h0);
    zero_stats_kernel<<<1,512>>>();
    { dim3 sb(32, 32); stats_kernel<<<128, sb>>>(h0, BB*4096, 32); }
    finalize_bn_kernel<<<1,512>>>(g1, b1, 32, 1.0/(double)(BB*4096));
    bnrelu32_kernel<<<(tot0+255)/256,256>>>(h0, tot0);

    // transition-down stages
    run_stage(x,  h0, p1, h1, 4096, 1024,  32,  64, W2, g2, b2, idx, nidx, gmax);
    run_stage(p1, h1, p2, h2, 1024,  256,  64, 128, W3, g3, b3, idx, nidx, gmax);
    run_stage(p2, h2, p3, h3,  256,   64, 128, 256, W4, g4, b4, idx, nidx, gmax);
    run_stage(p3, h3, p4, h4,   64,   16, 256, 512, W5, g5, b5, idx, nidx, gmax);

    // mean pool + head
    mean_kernel<<<(BB*512+255)/256,256>>>(h4);
    head_kernel<<<1,256>>>(z,  Wc1, bc1, gc1, hc1, t1, 512, 256, 1);
    head_kernel<<<1,128>>>(t1, Wc2, bc2, gc2, hc2, t2, 256, 128, 1);
    head_kernel<<<1, 64>>>(t2, Wc3, bc3, (const float*)0, (const float*)0, out, 128, 40, 0);
}

// round 9
// speedup vs baseline: 1.9069x; 1.0920x over previous
#include <cuda_runtime.h>
#include <cuda_bf16.h>
#include <math.h>

#define BB 16

// ---------------- scratch ----------------
__device__ float  g_h0[BB*4096*32];
__device__ float  g_h1[BB*1024*64];
__device__ float  g_h2[BB*256*128];
__device__ float  g_h3[BB*64*256];
__device__ float  g_h4[BB*16*512];
__device__ float  g_p1[BB*1024*3];
__device__ float  g_p2[BB*256*3];
__device__ float  g_p3[BB*64*3];
__device__ float  g_p4[BB*16*3];
__device__ int    g_idx[BB*1024];
__device__ int    g_nidx[BB*(1024+256+64+16)*16];   // per-stage offsets
__device__ float  g_gmax[BB*1024*64];
__device__ double g_sum[5][512], g_sqs[5][512];
__device__ float  g_z[BB*512];
__device__ float  g_t1[BB*256];
__device__ float  g_t2[BB*128];

// ---------------- zero all BN stats (once per launch) ----------------
__global__ void zero_all_kernel()
{
    int i = blockIdx.x * blockDim.x + threadIdx.x;
    if (i < 5*512) { (&g_sum[0][0])[i] = 0.0; (&g_sqs[0][0])[i] = 0.0; }
}

// ---------------- stage 0 linear ----------------
__global__ void lin0_kernel(const float* __restrict__ x, const float* __restrict__ W1,
                            float* __restrict__ h)
{
    int gid = blockIdx.x * blockDim.x + threadIdx.x;
    if (gid >= BB*4096*32) return;
    int d = gid & 31, r = gid >> 5;
    float v =        __ldg(x + r*3 + 0) * __ldg(W1 + d);
    v = fmaf(__ldg(x + r*3 + 1), __ldg(W1 + 32 + d), v);
    v = fmaf(__ldg(x + r*3 + 2), __ldg(W1 + 64 + d), v);
    h[gid] = v;
}

// ---------------- BN statistics (stage 0 only) ----------------
__global__ void stats_kernel(const float* __restrict__ y, int nrows, int C,
                             double* __restrict__ sumr, double* __restrict__ sqsr)
{
    int c  = threadIdx.x;
    int r0 = blockIdx.x * blockDim.y + threadIdx.y;
    int stride = gridDim.x * blockDim.y;
    double s = 0.0, q = 0.0;
    for (int r = r0; r < nrows; r += stride) {
        float v = y[(long long)r * C + c];
        s += (double)v;
        q += (double)v * (double)v;
    }
    atomicAdd(&sumr[c], s);
    atomicAdd(&sqsr[c], q);
}

// BN scale/shift computed per block in smem, then apply + relu (C=32)
__global__ void bnrelu32_kernel(float* __restrict__ h, int total,
                                const double* __restrict__ sumr, const double* __restrict__ sqsr,
                                const float* __restrict__ g, const float* __restrict__ b,
                                double inv_n)
{
    __shared__ float ssc[32], ssh[32];
    if (threadIdx.x < 32) {
        int c = threadIdx.x;
        double m = sumr[c] * inv_n;
        double v = sqsr[c] * inv_n - m * m;
        float rstd = (float)rsqrt(v + 1e-5);
        float sc = __ldg(g + c) * rstd;
        ssc[c] = sc; ssh[c] = __ldg(b + c) - (float)m * sc;
    }
    __syncthreads();
    int gid = blockIdx.x * blockDim.x + threadIdx.x;
    if (gid >= total) return;
    int c = gid & 31;
    float v = fmaf(h[gid], ssc[c], ssh[c]);
    h[gid] = v > 0.f ? v : 0.f;
}

// apply BN affine + relu to raw k-max (monotone affine commutes with max; gamma=1>0)
__global__ void bnapply_kernel(const float* __restrict__ gmax, float* __restrict__ hout,
                               int total, int C,
                               const double* __restrict__ sumr, const double* __restrict__ sqsr,
                               const float* __restrict__ g, const float* __restrict__ b,
                               double inv_n)
{
    __shared__ float ssc[512], ssh[512];
    for (int c = threadIdx.x; c < C; c += blockDim.x) {
        double m = sumr[c] * inv_n;
        double v = sqsr[c] * inv_n - m * m;
        float rstd = (float)rsqrt(v + 1e-5);
        float sc = __ldg(g + c) * rstd;
        ssc[c] = sc; ssh[c] = __ldg(b + c) - (float)m * sc;
    }
    __syncthreads();
    int gid = blockIdx.x * blockDim.x + threadIdx.x;
    if (gid >= total) return;
    int c = gid & (C - 1);
    float v = fmaf(gmax[gid], ssc[c], ssh[c]);
    hout[gid] = v > 0.f ? v : 0.f;
}

// ---------------- FPS v2: one barrier/iter ----------------
template<int N, int M, int T>
__global__ void __launch_bounds__(T) fps2_kernel(const float* __restrict__ p, int* __restrict__ out_idx)
{
    constexpr int P = N / T;
    constexpr int NW = T / 32;
    int b = blockIdx.x;
    const float* pb = p + (long long)b * N * 3;
    int tid = threadIdx.x, lane = tid & 31, w = tid >> 5;

    float px[P], py[P], pz[P], md[P];
#pragma unroll
    for (int i = 0; i < P; i++) {
        int n = tid + i * T;
        px[i] = __ldg(pb + 3*n); py[i] = __ldg(pb + 3*n + 1); pz[i] = __ldg(pb + 3*n + 2);
        md[i] = 3.4e38f;
    }

    __shared__ unsigned sv[2][NW];
    __shared__ unsigned si[2][NW];
    int last = 0;

    for (int m = 0; m < M; m++) {
        if (tid == 0) out_idx[b*M + m] = last;
        float lx = __ldg(pb + 3*last);
        float ly = __ldg(pb + 3*last + 1);
        float lz = __ldg(pb + 3*last + 2);

        float bestv = -1.0f; unsigned besti = 0;
#pragma unroll
        for (int i = 0; i < P; i++) {
            float dx = px[i] - lx, dy = py[i] - ly, dz = pz[i] - lz;
            float d = fmaf(dx, dx, fmaf(dy, dy, dz*dz));
            float mi = fminf(md[i], d);
            md[i] = mi;
            if (mi > bestv) { bestv = mi; besti = (unsigned)(tid + i*T); }
        }
        unsigned fb = __float_as_uint(bestv);
        unsigned wmax = __reduce_max_sync(0xffffffffu, fb);
        unsigned cand = (fb == wmax) ? besti : 0xffffffffu;
        unsigned widx = __reduce_min_sync(0xffffffffu, cand);
        int buf = m & 1;
        if (lane == 0) { sv[buf][w] = wmax; si[buf][w] = widx; }
        __syncthreads();
        unsigned vv = (lane < NW) ? sv[buf][lane] : 0u;
        unsigned ii = (lane < NW) ? si[buf][lane] : 0xffffffffu;
        unsigned m2 = __reduce_max_sync(0xffffffffu, vv);
        unsigned c2 = (vv == m2) ? ii : 0xffffffffu;
        last = (int)__reduce_min_sync(0xffffffffu, c2);
    }
}

// ---------------- gather points ----------------
__global__ void gather_p_kernel(const float* __restrict__ p_in, const int* __restrict__ idx,
                                float* __restrict__ p_out, int N, int M)
{
    int gid = blockIdx.x * blockDim.x + threadIdx.x;
    if (gid >= BB * M * 3) return;
    int c = gid % 3;
    int m = (gid / 3) % M;
    int b = gid / (3 * M);
    p_out[gid] = p_in[((long long)b * N + idx[b*M + m]) * 3 + c];
}

// ---------------- kNN with split-k candidate scan ----------------
#define KNN_TRY(PX,PY,PZ,NI) {                                                 \
    float dx = (PX) - qx, dy = (PY) - qy, dz = (PZ) - qz;                      \
    float d = fmaf(dx, dx, fmaf(dy, dy, dz*dz));                               \
    if (d < kd[15]) {                                                          \
        kd[15] = d; ki[15] = (NI);                                             \
        _Pragma("unroll")                                                      \
        for (int j = 15; j > 0; --j) {                                         \
            if (kd[j] < kd[j-1]) {                                             \
                float td = kd[j]; kd[j] = kd[j-1]; kd[j-1] = td;               \
                int   ti = ki[j]; ki[j] = ki[j-1]; ki[j-1] = ti;               \
            }                                                                  \
        }                                                                      \
    } }

template<int N, int QB, int SPLIT>
__global__ void __launch_bounds__(QB*SPLIT) knn_split_kernel(const float* __restrict__ p,
                                                             const float* __restrict__ q,
                                                             int M, int* __restrict__ nidx)
{
    constexpr int T = QB * SPLIT;
    constexpr int CHUNK = N / SPLIT;
    constexpr int CSTR = 16 * SPLIT + 1;
    extern __shared__ float sm[];
    float* sx = sm; float* sy = sm + N; float* sz = sm + 2*N;
    float* cd = sm + 3*N;
    int*   ci = (int*)(cd + QB*CSTR);

    int tid = threadIdx.x;
    int bpb = M / QB;
    int b  = blockIdx.x / bpb;
    int q0 = (blockIdx.x % bpb) * QB;
    const float* pb = p + (long long)b * N * 3;
    for (int i = tid; i < N; i += T) {
        sx[i] = pb[3*i]; sy[i] = pb[3*i+1]; sz[i] = pb[3*i+2];
    }
    __syncthreads();

    int qi   = tid % QB;
    int part = tid / QB;
    const float* qp = q + ((long long)b * M + q0 + qi) * 3;
    float qx = qp[0], qy = qp[1], qz = qp[2];

    float kd[16]; int ki[16];
#pragma unroll
    for (int i = 0; i < 16; i++) { kd[i] = 3.4e38f; ki[i] = 0; }

    int n_lo = part * CHUNK;
    for (int n0 = n_lo; n0 < n_lo + CHUNK; n0 += 4) {
        float4 X = *reinterpret_cast<const float4*>(sx + n0);
        float4 Y = *reinterpret_cast<const float4*>(sy + n0);
        float4 Z = *reinterpret_cast<const float4*>(sz + n0);
        KNN_TRY(X.x, Y.x, Z.x, n0 + 0);
        KNN_TRY(X.y, Y.y, Z.y, n0 + 1);
        KNN_TRY(X.z, Y.z, Z.z, n0 + 2);
        KNN_TRY(X.w, Y.w, Z.w, n0 + 3);
    }
    {
        float* d0 = cd + qi * CSTR + part * 16;
        int*   i0 = ci + qi * CSTR + part * 16;
#pragma unroll
        for (int j = 0; j < 16; j++) { d0[j] = kd[j]; i0[j] = ki[j]; }
    }
    __syncthreads();

    if (part == 0) {
        float md[16]; int mi[16];
#pragma unroll
        for (int i = 0; i < 16; i++) { md[i] = 3.4e38f; mi[i] = 0; }
        const float* d0 = cd + qi * CSTR;
        const int*   i0 = ci + qi * CSTR;
        for (int s = 0; s < 16 * SPLIT; s++) {
            float d = d0[s];
            if (d < md[15]) {
                md[15] = d; mi[15] = i0[s];
#pragma unroll
                for (int j = 15; j > 0; --j) {
                    if (md[j] < md[j-1]) {
                        float td = md[j]; md[j] = md[j-1]; md[j-1] = td;
                        int   ti = mi[j]; mi[j] = mi[j-1]; mi[j-1] = ti;
                    }
                }
            }
        }
        int base = ((long long)b * M + q0 + qi) * 16;
#pragma unroll
        for (int j = 0; j < 16; j++) nidx[base + j] = mi[j];
    }
}

// ---------------- fused GEMM ----------------
__global__ void __launch_bounds__(256) gemmF_kernel(
    const float* __restrict__ p_in, const float* __restrict__ h_in,
    const float* __restrict__ newp, const int* __restrict__ nidx,
    const float* __restrict__ W, float* __restrict__ gmax,
    int N, int M, int Cin, int COUT,
    double* __restrict__ sumr, double* __restrict__ sqsr)
{
    int CK = Cin + 3;
    __shared__ float As[16][68];
    __shared__ float Bs[16][68];
    __shared__ int sH[64], sP[64], sQ[64];
    int t = threadIdx.x;
    int row0 = blockIdx.x * 64;
    int col0 = blockIdx.y * 64;
    int tx = t & 15, ty = t >> 4;

    if (t < 64) {
        int r  = row0 + t;
        int n  = nidx[r];
        int bm = r >> 4;
        int b  = bm / M;
        sH[t] = (b * N + n) * Cin;
        sP[t] = (b * N + n) * 3;
        sQ[t] = bm * 3;
    }
    __syncthreads();

    float acc[4][4];
#pragma unroll
    for (int i = 0; i < 4; i++)
#pragma unroll
        for (int j = 0; j < 4; j++) acc[i][j] = 0.f;

    for (int k0 = 0; k0 < CK; k0 += 16) {
#pragma unroll
        for (int j = 0; j < 4; j++) {
            int lin = t + j * 256;
            int i = lin >> 4, kk = lin & 15;
            int c = k0 + kk;
            float v = 0.f;
            if (c < CK) {
                if (c < 3) v = __ldg(p_in + sP[i] + c) - __ldg(newp + sQ[i] + c);
                else       v = __ldg(h_in + sH[i] + c - 3);
            }
            As[kk][i] = v;
        }
#pragma unroll
        for (int j = 0; j < 4; j++) {
            int lin = t + j * 256;
            int kk = lin >> 6, cc = lin & 63;
            Bs[kk][cc] = (k0 + kk < CK) ? __ldg(W + (long long)(k0 + kk) * COUT + col0 + cc) : 0.f;
        }
        __syncthreads();
#pragma unroll
        for (int kk = 0; kk < 16; kk++) {
            float a0 = As[kk][ty*4+0], a1 = As[kk][ty*4+1], a2 = As[kk][ty*4+2], a3 = As[kk][ty*4+3];
            float b0 = Bs[kk][tx*4+0], b1 = Bs[kk][tx*4+1], b2 = Bs[kk][tx*4+2], b3 = Bs[kk][tx*4+3];
            acc[0][0]=fmaf(a0,b0,acc[0][0]); acc[0][1]=fmaf(a0,b1,acc[0][1]);
            acc[0][2]=fmaf(a0,b2,acc[0][2]); acc[0][3]=fmaf(a0,b3,acc[0][3]);
            acc[1][0]=fmaf(a1,b0,acc[1][0]); acc[1][1]=fmaf(a1,b1,acc[1][1]);
            acc[1][2]=fmaf(a1,b2,acc[1][2]); acc[1][3]=fmaf(a1,b3,acc[1][3]);
            acc[2][0]=fmaf(a2,b0,acc[2][0]); acc[2][1]=fmaf(a2,b1,acc[2][1]);
            acc[2][2]=fmaf(a2,b2,acc[2][2]); acc[2][3]=fmaf(a2,b3,acc[2][3]);
            acc[3][0]=fmaf(a3,b0,acc[3][0]); acc[3][1]=fmaf(a3,b1,acc[3][1]);
            acc[3][2]=fmaf(a3,b2,acc[3][2]); acc[3][3]=fmaf(a3,b3,acc[3][3]);
        }
        __syncthreads();
    }

    float cs[4], cq[4], cm[4];
#pragma unroll
    for (int j = 0; j < 4; j++) {
        cs[j] = acc[0][j] + acc[1][j] + acc[2][j] + acc[3][j];
        cq[j] = acc[0][j]*acc[0][j] + acc[1][j]*acc[1][j] + acc[2][j]*acc[2][j] + acc[3][j]*acc[3][j];
        cm[j] = fmaxf(fmaxf(acc[0][j], acc[1][j]), fmaxf(acc[2][j], acc[3][j]));
    }
#pragma unroll
    for (int j = 0; j < 4; j++) { As[ty][tx*4+j] = cs[j]; Bs[ty][tx*4+j] = cq[j]; }
    __syncthreads();
    if (t < 64) {
        double s = 0.0, q = 0.0;
#pragma unroll
        for (int r = 0; r < 16; r++) { s += (double)As[r][t]; q += (double)Bs[r][t]; }
        atomicAdd(&sumr[col0 + t], s);
        atomicAdd(&sqsr[col0 + t], q);
    }
    __syncthreads();
#pragma unroll
    for (int j = 0; j < 4; j++) As[ty][tx*4+j] = cm[j];
    __syncthreads();
    {
        int grp = t >> 6, col = t & 63;
        float mm = fmaxf(fmaxf(As[grp*4+0][col], As[grp*4+1][col]),
                         fmaxf(As[grp*4+2][col], As[grp*4+3][col]));
        gmax[(long long)((row0 >> 4) + grp) * COUT + col0 + col] = mm;
    }
}

// ---------------- mean pool ----------------
__global__ void mean_kernel(const float* __restrict__ h4)
{
    int gid = blockIdx.x * blockDim.x + threadIdx.x;
    if (gid >= BB * 512) return;
    int c = gid & 511, b = gid >> 9;
    float s = 0.f;
#pragma unroll
    for (int k = 0; k < 16; k++) s += h4[((long long)b * 16 + k) * 512 + c];
    g_z[gid] = s * (1.f / 16.f);
}

// ---------------- classifier head ----------------
__global__ void head_kernel(const float* __restrict__ in, const float* __restrict__ W,
                            const float* __restrict__ bias,
                            const float* __restrict__ gg, const float* __restrict__ bb,
                            float* __restrict__ outp, int Cin, int Cout, int bn_relu)
{
    __shared__ float s_in[16*512];
    int tid = threadIdx.x;
    for (int i = tid; i < 16*Cin; i += blockDim.x) s_in[i] = in[i];
    __syncthreads();

    int j = blockIdx.x * blockDim.x + tid;
    if (j >= Cout) return;
    float acc[16];
    float bs = __ldg(bias + j);
#pragma unroll
    for (int b = 0; b < 16; b++) acc[b] = bs;
    for (int c = 0; c < Cin; c++) {
        float w = __ldg(W + (long long)c * Cout + j);
#pragma unroll
        for (int b = 0; b < 16; b++) acc[b] = fmaf(s_in[b*Cin + c], w, acc[b]);
    }
    if (bn_relu) {
        float s = 0.f;
#pragma unroll
        for (int b = 0; b < 16; b++) s += acc[b];
        float m = s * (1.f/16.f);
        float v = 0.f;
#pragma unroll
        for (int b = 0; b < 16; b++) { float d = acc[b] - m; v = fmaf(d, d, v); }
        v *= (1.f/16.f);
        float sc = __ldg(gg + j) * rsqrtf(v + 1e-5f);
        float sh = __ldg(bb + j) - m * sc;
#pragma unroll
        for (int b = 0; b < 16; b++) {
            float o = fmaf(acc[b], sc, sh);
            outp[b*Cout + j] = o > 0.f ? o : 0.f;
        }
    } else {
#pragma unroll
        for (int b = 0; b < 16; b++) outp[b*Cout + j] = acc[b];
    }
}

// ---------------- host ----------------
static void run_fps(const float* p, int* idx, int N, cudaStream_t st)
{
    if      (N == 4096) fps2_kernel<4096,1024,512><<<BB,512,0,st>>>(p, idx);
    else if (N == 1024) fps2_kernel<1024, 256,512><<<BB,512,0,st>>>(p, idx);
    else if (N ==  256) fps2_kernel< 256,  64,256><<<BB,256,0,st>>>(p, idx);
    else                fps2_kernel<  64,  16, 64><<<BB, 64,0,st>>>(p, idx);
}

static void run_knn(const float* p, const float* q, int N, int M, int* nidx, cudaStream_t st)
{
    if (N == 4096) {
        constexpr int QB = 64, SP = 4;
        size_t smem = 3*4096*4 + (size_t)QB*(16*SP+1)*8;
        knn_split_kernel<4096,QB,SP><<<BB*(M/QB), QB*SP, smem, st>>>(p, q, M, nidx);
    } else if (N == 1024) {
        constexpr int QB = 32, SP = 4;
        size_t smem = 3*1024*4 + (size_t)QB*(16*SP+1)*8;
        knn_split_kernel<1024,QB,SP><<<BB*(M/QB), QB*SP, smem, st>>>(p, q, M, nidx);
    } else if (N == 256) {
        constexpr int QB = 16, SP = 4;
        size_t smem = 3*256*4 + (size_t)QB*(16*SP+1)*8;
        knn_split_kernel<256,QB,SP><<<BB*(M/QB), QB*SP, smem, st>>>(p, q, M, nidx);
    } else {
        constexpr int QB = 16, SP = 4;
        size_t smem = 3*64*4 + (size_t)QB*(16*SP+1)*8;
        knn_split_kernel<64,QB,SP><<<BB*(M/QB), QB*SP, smem, st>>>(p, q, M, nidx);
    }
}

extern "C" void kernel_launch(void* const* d_in, const int* in_sizes, int n_in,
                              void* d_out, int out_size)
{
    const float* x   = (const float*)d_in[0];
    const float* W1  = (const float*)d_in[1];
    const float* g1  = (const float*)d_in[2];
    const float* b1  = (const float*)d_in[3];
    const float* Ws[4]  = {(const float*)d_in[4], (const float*)d_in[7], (const float*)d_in[10], (const float*)d_in[13]};
    const float* gs[4]  = {(const float*)d_in[5], (const float*)d_in[8], (const float*)d_in[11], (const float*)d_in[14]};
    const float* bs[4]  = {(const float*)d_in[6], (const float*)d_in[9], (const float*)d_in[12], (const float*)d_in[15]};
    const float* Wc1 = (const float*)d_in[16];
    const float* bc1 = (const float*)d_in[17];
    const float* gc1 = (const float*)d_in[18];
    const float* hc1 = (const float*)d_in[19];
    const float* Wc2 = (const float*)d_in[20];
    const float* bc2 = (const float*)d_in[21];
    const float* gc2 = (const float*)d_in[22];
    const float* hc2 = (const float*)d_in[23];
    const float* Wc3 = (const float*)d_in[24];
    const float* bc3 = (const float*)d_in[25];
    float* out = (float*)d_out;

    // ---- stream / event setup (one-time resource creation, no device mem) ----
    static cudaStream_t sF = 0, sK = 0;
    static cudaEvent_t eRoot, eG[4], eK[4], eF;
    static bool inited = false;
    if (!inited) {
        cudaStreamCreateWithFlags(&sF, cudaStreamNonBlocking);
        cudaStreamCreateWithFlags(&sK, cudaStreamNonBlocking);
        cudaEventCreateWithFlags(&eRoot, cudaEventDisableTiming);
        cudaEventCreateWithFlags(&eF,    cudaEventDisableTiming);
        for (int i = 0; i < 4; i++) {
            cudaEventCreateWithFlags(&eG[i], cudaEventDisableTiming);
            cudaEventCreateWithFlags(&eK[i], cudaEventDisableTiming);
        }
        size_t smem1 = 3*4096*4 + (size_t)64*(16*4+1)*8;
        cudaFuncSetAttribute(knn_split_kernel<4096,64,4>,
                             cudaFuncAttributeMaxDynamicSharedMemorySize, (int)smem1);
        inited = true;
    }

    float *h0, *h1, *h2, *h3, *h4, *p1, *p2, *p3, *p4, *gmax, *z, *t1, *t2;
    int *idx, *nidx;
    double *sumB, *sqsB;
    cudaGetSymbolAddress((void**)&h0,   g_h0);
    cudaGetSymbolAddress((void**)&h1,   g_h1);
    cudaGetSymbolAddress((void**)&h2,   g_h2);
    cudaGetSymbolAddress((void**)&h3,   g_h3);
    cudaGetSymbolAddress((void**)&h4,   g_h4);
    cudaGetSymbolAddress((void**)&p1,   g_p1);
    cudaGetSymbolAddress((void**)&p2,   g_p2);
    cudaGetSymbolAddress((void**)&p3,   g_p3);
    cudaGetSymbolAddress((void**)&p4,   g_p4);
    cudaGetSymbolAddress((void**)&gmax, g_gmax);
    cudaGetSymbolAddress((void**)&z,    g_z);
    cudaGetSymbolAddress((void**)&t1,   g_t1);
    cudaGetSymbolAddress((void**)&t2,   g_t2);
    cudaGetSymbolAddress((void**)&idx,  g_idx);
    cudaGetSymbolAddress((void**)&nidx, g_nidx);
    cudaGetSymbolAddress((void**)&sumB, g_sum);
    cudaGetSymbolAddress((void**)&sqsB, g_sqs);

    const float* pin[4]  = {x,  p1, p2, p3};
    float*       pout[4] = {p1, p2, p3, p4};
    const float* hin[4]  = {h0, h1, h2, h3};
    float*       hout[4] = {h1, h2, h3, h4};
    const int    Ns[4]   = {4096, 1024, 256, 64};
    const int    Ms[4]   = {1024, 256, 64, 16};
    const int    Cin_[4] = {32, 64, 128, 256};
    const int    Cout_[4]= {64, 128, 256, 512};
    int nidxOff[4]; nidxOff[0] = 0;
    for (int s = 1; s < 4; s++) nidxOff[s] = nidxOff[s-1] + BB * Ms[s-1] * 16;

    // ---- fork point ----
    cudaEventRecord(eRoot, 0);
    cudaStreamWaitEvent(sF, eRoot, 0);
    cudaStreamWaitEvent(sK, eRoot, 0);

    // ---- sF: FPS + gather chain (depends only on coordinates) ----
    for (int s = 0; s < 4; s++) {
        run_fps(pin[s], idx, Ns[s], sF);
        int t3 = BB * Ms[s] * 3;
        gather_p_kernel<<<(t3+255)/256,256,0,sF>>>(pin[s], idx, pout[s], Ns[s], Ms[s]);
        cudaEventRecord(eG[s], sF);
    }
    cudaEventRecord(eF, sF);

    // ---- sK: kNN per stage once its gather lands ----
    for (int s = 0; s < 4; s++) {
        cudaStreamWaitEvent(sK, eG[s], 0);
        run_knn(pin[s], pout[s], Ns[s], Ms[s], nidx + nidxOff[s], sK);
        cudaEventRecord(eK[s], sK);
    }

    // ---- main stream: stats zero + stage 0 (concurrent with FPS chain) ----
    zero_all_kernel<<<10,256>>>();
    int tot0 = BB*4096*32;
    lin0_kernel<<<(tot0+255)/256,256>>>(x, W1, h0);
    { dim3 sb(32, 32); stats_kernel<<<128, sb>>>(h0, BB*4096, 32, sumB, sqsB); }
    bnrelu32_kernel<<<(tot0+255)/256,256>>>(h0, tot0, sumB, sqsB, g1, b1, 1.0/(double)(BB*4096));

    // ---- main stream: GEMM + BN chain ----
    for (int s = 0; s < 4; s++) {
        cudaStreamWaitEvent(0, eK[s], 0);
        int rows = BB * Ms[s] * 16;
        dim3 gg(rows/64, Cout_[s]/64);
        gemmF_kernel<<<gg, 256>>>(pin[s], hin[s], pout[s], nidx + nidxOff[s],
                                  Ws[s], gmax, Ns[s], Ms[s], Cin_[s], Cout_[s],
                                  sumB + (s+1)*512, sqsB + (s+1)*512);
        int bm = BB * Ms[s];
        bnapply_kernel<<<(bm*Cout_[s]+255)/256,256>>>(gmax, hout[s], bm*Cout_[s], Cout_[s],
                                                      sumB + (s+1)*512, sqsB + (s+1)*512,
                                                      gs[s], bs[s], 1.0/(double)rows);
    }
    cudaStreamWaitEvent(0, eF, 0);

    // ---- head ----
    mean_kernel<<<(BB*512+255)/256,256>>>(h4);
    head_kernel<<<1,256>>>(z,  Wc1, bc1, gc1, hc1, t1, 512, 256, 1);
    head_kernel<<<1,128>>>(t1, Wc2, bc2, gc2, hc2, t2, 256, 128, 1);
    head_kernel<<<1, 64>>>(t2, Wc3, bc3, (const float*)0, (const float*)0, out, 128, 40, 0);
}